// round 8
// baseline (speedup 1.0000x reference)
#include <cuda_runtime.h>
#include <cuda_fp16.h>
#include <cstdint>

#define D_DIM   128
#define NPOS    512
#define K_DIM   2048
#define R_MAX   49152    // B*H*Q = 2*12*2048

// 50 MB scratch: fp16 interpolation tables (512 entries per (b,h,q) row).
__device__ __half g_table[(size_t)R_MAX * NPOS];

// ---------------------------------------------------------------------------
// mma.sync m16n8k16 row.col f32.f16.f16.f32  (tensor pipe, sm_80+ PTX)
// ---------------------------------------------------------------------------
__device__ __forceinline__ void mma_f16(float* d, const uint32_t* a, const uint32_t* b) {
    asm volatile(
        "mma.sync.aligned.m16n8k16.row.col.f32.f16.f16.f32 "
        "{%0,%1,%2,%3}, {%4,%5,%6,%7}, {%8,%9}, {%0,%1,%2,%3};"
        : "+f"(d[0]), "+f"(d[1]), "+f"(d[2]), "+f"(d[3])
        : "r"(a[0]), "r"(a[1]), "r"(a[2]), "r"(a[3]), "r"(b[0]), "r"(b[1]));
}

__device__ __forceinline__ void ldsm_x4(uint32_t* r, uint32_t addr) {
    asm volatile("ldmatrix.sync.aligned.m8n8.x4.shared.b16 {%0,%1,%2,%3}, [%4];"
        : "=r"(r[0]), "=r"(r[1]), "=r"(r[2]), "=r"(r[3]) : "r"(addr));
}
__device__ __forceinline__ void ldsm_x4_t(uint32_t* r, uint32_t addr) {
    asm volatile("ldmatrix.sync.aligned.m8n8.x4.trans.shared.b16 {%0,%1,%2,%3}, [%4];"
        : "=r"(r[0]), "=r"(r[1]), "=r"(r[2]), "=r"(r[3]) : "r"(addr));
}

__device__ __forceinline__ uint32_t smem_u32(const void* p) {
    uint32_t a;
    asm("{ .reg .u64 t; cvta.to.shared.u64 t, %1; cvt.u32.u64 %0, t; }" : "=r"(a) : "l"(p));
    return a;
}

// ============================================================================
// Kernel A: T[R,512] = Q[R,128] @ P[128,512], single-pass fp16 mma.
// Block 128(M) x 256(N), 512 threads, 16 warps (4M x 4N), warp tile m32 x n64.
// smem 100 KB -> occupancy 2 (8 warps/SMSP). A [m][k] stride 272 B,
// B [k][n] stride 528 B (stride%128B = 16 -> ldmatrix conflict-free).
// ============================================================================
#define SSTR_A    272
#define SSTR_B    528
#define SM_A      0
#define SM_B      34816          // 128*272
#define SM_TOTAL  102400         // 34816 + 128*528

__global__ __launch_bounds__(512, 2)
void cope_gemm_mma(const float* __restrict__ Q,   // [R,128]
                   const float* __restrict__ P) { // [128,512]
    extern __shared__ char sm[];
    const int tid  = threadIdx.x;
    const int lane = tid & 31;
    const int wid  = tid >> 5;
    const int r0   = blockIdx.y * 128;
    const int n0   = blockIdx.x * 256;

    // ---- load A tile: 128 rows x K=128, fp32 -> fp16, [m][k] ----
    {
        int r  = tid >> 2;               // 0..127
        int c0 = (tid & 3) * 32;         // 32 k-floats per thread
        const float4* src = (const float4*)(Q + (size_t)(r0 + r) * D_DIM + c0);
        char* dst = sm + SM_A + r * SSTR_A + c0 * 2;
        #pragma unroll
        for (int i = 0; i < 8; i++) {
            float4 v = src[i];
            __half2 h0 = __floats2half2_rn(v.x, v.y);
            __half2 h1 = __floats2half2_rn(v.z, v.w);
            uint2 w;
            w.x = *(uint32_t*)&h0;
            w.y = *(uint32_t*)&h1;
            *(uint2*)(dst + i * 8) = w;
        }
    }

    // ---- load B tile k-major: sB[k][n] = P[k][n0+n], 256 wide, fp16 ----
    {
        int k  = tid >> 2;               // 0..127
        int c0 = (tid & 3) * 64;         // 64 n-floats per thread
        const float4* src = (const float4*)(P + (size_t)k * NPOS + n0 + c0);
        char* dst = sm + SM_B + k * SSTR_B + c0 * 2;
        #pragma unroll
        for (int i = 0; i < 16; i++) {
            float4 v = src[i];
            __half2 h0 = __floats2half2_rn(v.x, v.y);
            __half2 h1 = __floats2half2_rn(v.z, v.w);
            uint2 w;
            w.x = *(uint32_t*)&h0;
            w.y = *(uint32_t*)&h1;
            *(uint2*)(dst + i * 8) = w;
        }
    }
    __syncthreads();

    const int g = lane >> 2;             // 0..7
    const int t = lane & 3;              // 0..3
    const int mrow = (wid & 3) * 32;     // 4 warps along M
    const int ncol = (wid >> 2) * 64;    // 4 warps along N

    const uint32_t smb = smem_u32(sm);
    const uint32_t a_off = (uint32_t)((mrow + ((lane >> 3) & 1) * 8 + (lane & 7)) * SSTR_A
                                      + (lane >> 4) * 16);
    const uint32_t b_off = (uint32_t)((((lane >> 3) & 1) * 8 + (lane & 7)) * SSTR_B
                                      + (lane >> 4) * 16 + ncol * 2);

    float acc[2][8][4];                  // [mf][nf][c]
    #pragma unroll
    for (int mf = 0; mf < 2; mf++)
        #pragma unroll
        for (int nf = 0; nf < 8; nf++)
            #pragma unroll
            for (int c = 0; c < 4; c++) acc[mf][nf][c] = 0.0f;

    #pragma unroll
    for (int ks = 0; ks < 8; ks++) {
        const uint32_t kb = ks * 32;     // A byte offset along k
        uint32_t a[2][4];
        #pragma unroll
        for (int mf = 0; mf < 2; mf++)
            ldsm_x4(a[mf], smb + SM_A + mf * 16 * SSTR_A + a_off + kb);
        uint32_t b[4][4];                // p covers nf=2p, 2p+1
        #pragma unroll
        for (int p = 0; p < 4; p++)
            ldsm_x4_t(b[p], smb + SM_B + ks * 16 * SSTR_B + b_off + p * 32);

        #pragma unroll
        for (int mf = 0; mf < 2; mf++)
            #pragma unroll
            for (int p = 0; p < 4; p++) {
                mma_f16(acc[mf][2 * p],     a[mf], &b[p][0]);
                mma_f16(acc[mf][2 * p + 1], a[mf], &b[p][2]);
            }
    }

    // ---- epilogue: pack (c0,c1)/(c2,c3) column pairs as half2 ----
    #pragma unroll
    for (int mf = 0; mf < 2; mf++) {
        #pragma unroll
        for (int nf = 0; nf < 8; nf++) {
            size_t row = (size_t)(r0 + mrow + mf * 16 + g);
            size_t nn  = (size_t)(n0 + ncol + nf * 8 + t * 2);
            __half2 h0 = __floats2half2_rn(acc[mf][nf][0], acc[mf][nf][1]);
            __half2 h1 = __floats2half2_rn(acc[mf][nf][2], acc[mf][nf][3]);
            *(uint32_t*)(g_table + row * NPOS + nn)        = *(uint32_t*)&h0;
            *(uint32_t*)(g_table + (row + 8) * NPOS + nn)  = *(uint32_t*)&h1;
        }
    }
}

// ============================================================================
// Kernel B: per row — sigmoid, reversed cumsum, clamp, interp gather.
// Table staged as half2 pairs (t[i], t[i+1]) -> one LDS.32 per element.
// ============================================================================
__global__ __launch_bounds__(256)
void cope_gather_kernel(const float* __restrict__ attn,   // [R,2048]
                        const int*   __restrict__ nposp,
                        float*       __restrict__ out) {  // [R,2048]
    __shared__ __half    tabh[NPOS];
    __shared__ uint32_t  tab2u[NPOS];
    __shared__ float     wsum[8];

    const int row  = blockIdx.x;
    const int tid  = threadIdx.x;
    const int lane = tid & 31;
    const int wid  = tid >> 5;

    ((uint32_t*)tabh)[tid] =
        ((const uint32_t*)(g_table + (size_t)row * NPOS))[tid];

    const float* arow = attn + (size_t)row * K_DIM + tid * 8;
    float4 v0 = *(const float4*)(arow);
    float4 v1 = *(const float4*)(arow + 4);
    float gg[8] = {v0.x, v0.y, v0.z, v0.w, v1.x, v1.y, v1.z, v1.w};
    #pragma unroll
    for (int j = 0; j < 8; j++)
        gg[j] = __fdividef(1.0f, 1.0f + __expf(-gg[j]));

    __syncthreads();
    {
        __half a = tabh[tid], b = tabh[tid + 1];
        __half2 h; h.x = a; h.y = b;
        tab2u[tid] = *(uint32_t*)&h;
        int i2 = tid + 256;
        __half a2 = tabh[i2];
        __half b2 = (i2 == NPOS - 1) ? a2 : tabh[i2 + 1];
        __half2 h2; h2.x = a2; h2.y = b2;
        tab2u[i2] = *(uint32_t*)&h2;
    }

    float ls[8];
    ls[7] = gg[7];
    #pragma unroll
    for (int j = 6; j >= 0; j--) ls[j] = gg[j] + ls[j + 1];

    float v = ls[0];
    #pragma unroll
    for (int d = 1; d < 32; d <<= 1) {
        float tt = __shfl_up_sync(0xffffffffu, v, d);
        if (lane >= d) v += tt;
    }
    if (lane == 31) wsum[wid] = v;
    __syncthreads();

    float wpre = 0.0f, total = 0.0f;
    #pragma unroll
    for (int w = 0; w < 8; w++) {
        float x = wsum[w];
        total += x;
        if (w < wid) wpre += x;
    }
    float offset = total - (wpre + v);

    const float npmf = (float)(*nposp - 1);

    float oo[8];
    #pragma unroll
    for (int j = 0; j < 8; j++) {
        float p  = fminf(offset + ls[j], npmf);
        float pf = floorf(p);
        float w  = p - pf;
        uint32_t pv = tab2u[(int)pf];
        float2 f = __half22float2(*(__half2*)&pv);
        oo[j] = fmaf(w, f.y - f.x, f.x);
    }

    float* orow = out + (size_t)row * K_DIM + tid * 8;
    *(float4*)(orow)     = make_float4(oo[0], oo[1], oo[2], oo[3]);
    *(float4*)(orow + 4) = make_float4(oo[4], oo[5], oo[6], oo[7]);
}

// ---------------------------------------------------------------------------
extern "C" void kernel_launch(void* const* d_in, const int* in_sizes, int n_in,
                              void* d_out, int out_size) {
    const float* q    = (const float*)d_in[0];   // [B,H,Q,D]
    const float* attn = (const float*)d_in[1];   // [B,H,Q,K]
    const float* pe   = (const float*)d_in[2];   // [1,D,NPOS]
    const int*   npos = (const int*)d_in[3];
    float*       out  = (float*)d_out;

    const int R = in_sizes[0] / D_DIM;           // 49152

    cudaFuncSetAttribute(cope_gemm_mma,
                         cudaFuncAttributeMaxDynamicSharedMemorySize, SM_TOTAL);
    dim3 gA(NPOS / 256, R / 128);
    cope_gemm_mma<<<gA, 512, SM_TOTAL>>>(q, pe);

    cope_gather_kernel<<<R, 256>>>(attn, npos, out);

    (void)n_in; (void)out_size;
}

// round 9
// speedup vs baseline: 1.2587x; 1.2587x over previous
#include <cuda_runtime.h>
#include <cuda_fp16.h>
#include <cstdint>

#define D_DIM   128
#define NPOS    512
#define K_DIM   2048
#define R_MAX   49152    // B*H*Q = 2*12*2048

// 50 MB scratch: fp16 interpolation tables (512 entries per (b,h,q) row).
__device__ __half g_table[(size_t)R_MAX * NPOS];

// ---------------------------------------------------------------------------
// mma.sync m16n8k16 row.col f32.f16.f16.f32  (tensor pipe, sm_80+ PTX)
// ---------------------------------------------------------------------------
__device__ __forceinline__ void mma_f16(float* d, const uint32_t* a, const uint32_t* b) {
    asm volatile(
        "mma.sync.aligned.m16n8k16.row.col.f32.f16.f16.f32 "
        "{%0,%1,%2,%3}, {%4,%5,%6,%7}, {%8,%9}, {%0,%1,%2,%3};"
        : "+f"(d[0]), "+f"(d[1]), "+f"(d[2]), "+f"(d[3])
        : "r"(a[0]), "r"(a[1]), "r"(a[2]), "r"(a[3]), "r"(b[0]), "r"(b[1]));
}

__device__ __forceinline__ void ldsm_x4(uint32_t* r, uint32_t addr) {
    asm volatile("ldmatrix.sync.aligned.m8n8.x4.shared.b16 {%0,%1,%2,%3}, [%4];"
        : "=r"(r[0]), "=r"(r[1]), "=r"(r[2]), "=r"(r[3]) : "r"(addr));
}
__device__ __forceinline__ void ldsm_x4_t(uint32_t* r, uint32_t addr) {
    asm volatile("ldmatrix.sync.aligned.m8n8.x4.trans.shared.b16 {%0,%1,%2,%3}, [%4];"
        : "=r"(r[0]), "=r"(r[1]), "=r"(r[2]), "=r"(r[3]) : "r"(addr));
}

__device__ __forceinline__ uint32_t smem_u32(const void* p) {
    uint32_t a;
    asm("{ .reg .u64 t; cvta.to.shared.u64 t, %1; cvt.u32.u64 %0, t; }" : "=r"(a) : "l"(p));
    return a;
}

// ============================================================================
// Kernel A: T[R,512] = Q[R,128] @ P[128,512], single-pass fp16 mma.
// Block 128(M) x 128(N), 256 threads, 8 warps (4M x 2N), warp tile m32 x n64.
// smem 69.6 KB, __launch_bounds__(256,2) -> occ 2 (4 warps/SMSP), ~105 regs
// (no spills: 64 acc + 24 frags + addr). Strides 272 B -> ldmatrix
// conflict-free.
// ============================================================================
#define SSTR      272
#define SM_A      0
#define SM_B      34816          // 128*272
#define SM_TOTAL  69632          // 2 * 128*272

__global__ __launch_bounds__(256, 2)
void cope_gemm_mma(const float* __restrict__ Q,   // [R,128]
                   const float* __restrict__ P) { // [128,512]
    extern __shared__ char sm[];
    const int tid  = threadIdx.x;
    const int lane = tid & 31;
    const int wid  = tid >> 5;
    const int r0   = blockIdx.y * 128;
    const int n0   = blockIdx.x * 128;

    // ---- load A tile: 128 rows x K=128, fp32 -> fp16, [m][k] ----
    {
        int r  = tid >> 1;               // 0..127
        int c0 = (tid & 1) * 64;         // 64 k-floats per thread
        const float4* src = (const float4*)(Q + (size_t)(r0 + r) * D_DIM + c0);
        char* dst = sm + SM_A + r * SSTR + c0 * 2;
        #pragma unroll
        for (int i = 0; i < 16; i++) {
            float4 v = src[i];
            __half2 h0 = __floats2half2_rn(v.x, v.y);
            __half2 h1 = __floats2half2_rn(v.z, v.w);
            uint2 w;
            w.x = *(uint32_t*)&h0;
            w.y = *(uint32_t*)&h1;
            *(uint2*)(dst + i * 8) = w;
        }
    }

    // ---- load B tile k-major: sB[k][n] = P[k][n0+n], fp16 ----
    {
        int k  = tid >> 1;               // 0..127
        int c0 = (tid & 1) * 64;         // 64 n-floats per thread
        const float4* src = (const float4*)(P + (size_t)k * NPOS + n0 + c0);
        char* dst = sm + SM_B + k * SSTR + c0 * 2;
        #pragma unroll
        for (int i = 0; i < 16; i++) {
            float4 v = src[i];
            __half2 h0 = __floats2half2_rn(v.x, v.y);
            __half2 h1 = __floats2half2_rn(v.z, v.w);
            uint2 w;
            w.x = *(uint32_t*)&h0;
            w.y = *(uint32_t*)&h1;
            *(uint2*)(dst + i * 8) = w;
        }
    }
    __syncthreads();

    const int g = lane >> 2;             // 0..7
    const int t = lane & 3;              // 0..3
    const int mrow = (wid & 3) * 32;     // 4 warps along M
    const int ncol = (wid >> 2) * 64;    // 2 warps along N

    const uint32_t smb = smem_u32(sm);
    const uint32_t a_off = (uint32_t)((mrow + ((lane >> 3) & 1) * 8 + (lane & 7)) * SSTR
                                      + (lane >> 4) * 16);
    const uint32_t b_off = (uint32_t)((((lane >> 3) & 1) * 8 + (lane & 7)) * SSTR
                                      + (lane >> 4) * 16 + ncol * 2);

    float acc[2][8][4];                  // [mf][nf][c]
    #pragma unroll
    for (int mf = 0; mf < 2; mf++)
        #pragma unroll
        for (int nf = 0; nf < 8; nf++)
            #pragma unroll
            for (int c = 0; c < 4; c++) acc[mf][nf][c] = 0.0f;

    #pragma unroll
    for (int ks = 0; ks < 8; ks++) {
        const uint32_t kb = ks * 32;     // A byte offset along k
        uint32_t a[2][4];
        #pragma unroll
        for (int mf = 0; mf < 2; mf++)
            ldsm_x4(a[mf], smb + SM_A + mf * 16 * SSTR + a_off + kb);
        uint32_t b[4][4];                // p covers nf=2p, 2p+1
        #pragma unroll
        for (int p = 0; p < 4; p++)
            ldsm_x4_t(b[p], smb + SM_B + ks * 16 * SSTR + b_off + p * 32);

        #pragma unroll
        for (int mf = 0; mf < 2; mf++)
            #pragma unroll
            for (int p = 0; p < 4; p++) {
                mma_f16(acc[mf][2 * p],     a[mf], &b[p][0]);
                mma_f16(acc[mf][2 * p + 1], a[mf], &b[p][2]);
            }
    }

    // ---- epilogue: pack (c0,c1)/(c2,c3) column pairs as half2 ----
    #pragma unroll
    for (int mf = 0; mf < 2; mf++) {
        #pragma unroll
        for (int nf = 0; nf < 8; nf++) {
            size_t row = (size_t)(r0 + mrow + mf * 16 + g);
            size_t nn  = (size_t)(n0 + ncol + nf * 8 + t * 2);
            __half2 h0 = __floats2half2_rn(acc[mf][nf][0], acc[mf][nf][1]);
            __half2 h1 = __floats2half2_rn(acc[mf][nf][2], acc[mf][nf][3]);
            *(uint32_t*)(g_table + row * NPOS + nn)        = *(uint32_t*)&h0;
            *(uint32_t*)(g_table + (row + 8) * NPOS + nn)  = *(uint32_t*)&h1;
        }
    }
}

// ============================================================================
// Kernel B: per row — sigmoid, reversed cumsum, clamp, interp gather.
// Table staged as half2 pairs (t[i], t[i+1]) -> one LDS.32 per element.
// ============================================================================
__global__ __launch_bounds__(256)
void cope_gather_kernel(const float* __restrict__ attn,   // [R,2048]
                        const int*   __restrict__ nposp,
                        float*       __restrict__ out) {  // [R,2048]
    __shared__ __half    tabh[NPOS];
    __shared__ uint32_t  tab2u[NPOS];
    __shared__ float     wsum[8];

    const int row  = blockIdx.x;
    const int tid  = threadIdx.x;
    const int lane = tid & 31;
    const int wid  = tid >> 5;

    ((uint32_t*)tabh)[tid] =
        ((const uint32_t*)(g_table + (size_t)row * NPOS))[tid];

    const float* arow = attn + (size_t)row * K_DIM + tid * 8;
    float4 v0 = *(const float4*)(arow);
    float4 v1 = *(const float4*)(arow + 4);
    float gg[8] = {v0.x, v0.y, v0.z, v0.w, v1.x, v1.y, v1.z, v1.w};
    #pragma unroll
    for (int j = 0; j < 8; j++)
        gg[j] = __fdividef(1.0f, 1.0f + __expf(-gg[j]));

    __syncthreads();
    {
        __half a = tabh[tid], b = tabh[tid + 1];
        __half2 h; h.x = a; h.y = b;
        tab2u[tid] = *(uint32_t*)&h;
        int i2 = tid + 256;
        __half a2 = tabh[i2];
        __half b2 = (i2 == NPOS - 1) ? a2 : tabh[i2 + 1];
        __half2 h2; h2.x = a2; h2.y = b2;
        tab2u[i2] = *(uint32_t*)&h2;
    }

    float ls[8];
    ls[7] = gg[7];
    #pragma unroll
    for (int j = 6; j >= 0; j--) ls[j] = gg[j] + ls[j + 1];

    float v = ls[0];
    #pragma unroll
    for (int d = 1; d < 32; d <<= 1) {
        float tt = __shfl_up_sync(0xffffffffu, v, d);
        if (lane >= d) v += tt;
    }
    if (lane == 31) wsum[wid] = v;
    __syncthreads();

    float wpre = 0.0f, total = 0.0f;
    #pragma unroll
    for (int w = 0; w < 8; w++) {
        float x = wsum[w];
        total += x;
        if (w < wid) wpre += x;
    }
    float offset = total - (wpre + v);

    const float npmf = (float)(*nposp - 1);

    float oo[8];
    #pragma unroll
    for (int j = 0; j < 8; j++) {
        float p  = fminf(offset + ls[j], npmf);
        float pf = floorf(p);
        float w  = p - pf;
        uint32_t pv = tab2u[(int)pf];
        float2 f = __half22float2(*(__half2*)&pv);
        oo[j] = fmaf(w, f.y - f.x, f.x);
    }

    float* orow = out + (size_t)row * K_DIM + tid * 8;
    *(float4*)(orow)     = make_float4(oo[0], oo[1], oo[2], oo[3]);
    *(float4*)(orow + 4) = make_float4(oo[4], oo[5], oo[6], oo[7]);
}

// ---------------------------------------------------------------------------
extern "C" void kernel_launch(void* const* d_in, const int* in_sizes, int n_in,
                              void* d_out, int out_size) {
    const float* q    = (const float*)d_in[0];   // [B,H,Q,D]
    const float* attn = (const float*)d_in[1];   // [B,H,Q,K]
    const float* pe   = (const float*)d_in[2];   // [1,D,NPOS]
    const int*   npos = (const int*)d_in[3];
    float*       out  = (float*)d_out;

    const int R = in_sizes[0] / D_DIM;           // 49152

    cudaFuncSetAttribute(cope_gemm_mma,
                         cudaFuncAttributeMaxDynamicSharedMemorySize, SM_TOTAL);
    dim3 gA(NPOS / 128, R / 128);
    cope_gemm_mma<<<gA, 256, SM_TOTAL>>>(q, pe);

    cope_gather_kernel<<<R, 256>>>(attn, npos, out);

    (void)n_in; (void)out_size;
}

// round 12
// speedup vs baseline: 1.3446x; 1.0682x over previous
#include <cuda_runtime.h>
#include <cuda_fp16.h>
#include <cstdint>

#define D_DIM   128
#define NPOS    512
#define K_DIM   2048
#define R_MAX   49152    // B*H*Q = 2*12*2048

// 50 MB scratch: fp16 interpolation tables (512 entries per (b,h,q) row).
__device__ __half g_table[(size_t)R_MAX * NPOS];

// ---------------------------------------------------------------------------
// mma.sync m16n8k16 row.col f32.f16.f16.f32  (tensor pipe, sm_80+ PTX)
// ---------------------------------------------------------------------------
__device__ __forceinline__ void mma_f16(float* d, const uint32_t* a, const uint32_t* b) {
    asm volatile(
        "mma.sync.aligned.m16n8k16.row.col.f32.f16.f16.f32 "
        "{%0,%1,%2,%3}, {%4,%5,%6,%7}, {%8,%9}, {%0,%1,%2,%3};"
        : "+f"(d[0]), "+f"(d[1]), "+f"(d[2]), "+f"(d[3])
        : "r"(a[0]), "r"(a[1]), "r"(a[2]), "r"(a[3]), "r"(b[0]), "r"(b[1]));
}

__device__ __forceinline__ void ldsm_x4(uint32_t* r, uint32_t addr) {
    asm volatile("ldmatrix.sync.aligned.m8n8.x4.shared.b16 {%0,%1,%2,%3}, [%4];"
        : "=r"(r[0]), "=r"(r[1]), "=r"(r[2]), "=r"(r[3]) : "r"(addr));
}
__device__ __forceinline__ void ldsm_x4_t(uint32_t* r, uint32_t addr) {
    asm volatile("ldmatrix.sync.aligned.m8n8.x4.trans.shared.b16 {%0,%1,%2,%3}, [%4];"
        : "=r"(r[0]), "=r"(r[1]), "=r"(r[2]), "=r"(r[3]) : "r"(addr));
}

__device__ __forceinline__ uint32_t smem_u32(const void* p) {
    uint32_t a;
    asm("{ .reg .u64 t; cvta.to.shared.u64 t, %1; cvt.u32.u64 %0, t; }" : "=r"(a) : "l"(p));
    return a;
}

// ============================================================================
// Kernel A: T[R,512] = Q[R,128] @ P[128,512], single-pass fp16 mma.
// One block per 128-row block (384 blocks, ~1.3 waves at occ 2), looping the
// 4 N-subtiles of 128 internally: A staged ONCE (no 4x redundant DRAM reads),
// B re-staged per subtile (L2-resident). 256 threads, 8 warps (4M x 2N),
// warp tile m32 x n64, smem 69.6 KB, occ 2, ~105 regs (no spills).
// ============================================================================
#define SSTR      272
#define SM_A      0
#define SM_B      34816          // 128*272
#define SM_TOTAL  69632          // 2 * 128*272

__global__ __launch_bounds__(256, 2)
void cope_gemm_mma(const float* __restrict__ Q,   // [R,128]
                   const float* __restrict__ P) { // [128,512]
    extern __shared__ char sm[];
    const int tid  = threadIdx.x;
    const int lane = tid & 31;
    const int wid  = tid >> 5;
    const int r0   = blockIdx.x * 128;

    // ---- stage A tile ONCE: 128 rows x K=128, fp32 -> fp16, [m][k] ----
    {
        int r  = tid >> 1;               // 0..127
        int c0 = (tid & 1) * 64;         // 64 k-floats per thread
        const float4* src = (const float4*)(Q + (size_t)(r0 + r) * D_DIM + c0);
        char* dst = sm + SM_A + r * SSTR + c0 * 2;
        #pragma unroll
        for (int i = 0; i < 16; i++) {
            float4 v = __ldcs(src + i);
            __half2 h0 = __floats2half2_rn(v.x, v.y);
            __half2 h1 = __floats2half2_rn(v.z, v.w);
            uint2 w;
            w.x = *(uint32_t*)&h0;
            w.y = *(uint32_t*)&h1;
            *(uint2*)(dst + i * 8) = w;
        }
    }

    const int g = lane >> 2;             // 0..7
    const int t = lane & 3;              // 0..3
    const int mrow = (wid & 3) * 32;     // 4 warps along M
    const int ncol = (wid >> 2) * 64;    // 2 warps along N

    const uint32_t smb = smem_u32(sm);
    const uint32_t a_off = (uint32_t)((mrow + ((lane >> 3) & 1) * 8 + (lane & 7)) * SSTR
                                      + (lane >> 4) * 16);
    const uint32_t b_off = (uint32_t)((((lane >> 3) & 1) * 8 + (lane & 7)) * SSTR
                                      + (lane >> 4) * 16 + ncol * 2);

    // B-staging indices (per thread)
    const int bk  = tid >> 1;            // 0..127
    const int bc0 = (tid & 1) * 64;      // 64 n-floats per thread

    for (int ns = 0; ns < 4; ns++) {
        const int n0 = ns * 128;

        // ---- stage B subtile k-major: sB[k][n] = P[k][n0+n], fp16 ----
        {
            const float4* src = (const float4*)(P + (size_t)bk * NPOS + n0 + bc0);
            char* dst = sm + SM_B + bk * SSTR + bc0 * 2;
            #pragma unroll
            for (int i = 0; i < 16; i++) {
                float4 v = src[i];
                __half2 h0 = __floats2half2_rn(v.x, v.y);
                __half2 h1 = __floats2half2_rn(v.z, v.w);
                uint2 w;
                w.x = *(uint32_t*)&h0;
                w.y = *(uint32_t*)&h1;
                *(uint2*)(dst + i * 8) = w;
            }
        }
        __syncthreads();

        float acc[2][8][4];              // [mf][nf][c]
        #pragma unroll
        for (int mf = 0; mf < 2; mf++)
            #pragma unroll
            for (int nf = 0; nf < 8; nf++)
                #pragma unroll
                for (int c = 0; c < 4; c++) acc[mf][nf][c] = 0.0f;

        #pragma unroll
        for (int ks = 0; ks < 8; ks++) {
            const uint32_t kb = ks * 32; // A byte offset along k
            uint32_t a[2][4];
            #pragma unroll
            for (int mf = 0; mf < 2; mf++)
                ldsm_x4(a[mf], smb + SM_A + mf * 16 * SSTR + a_off + kb);
            uint32_t b[4][4];            // p covers nf=2p, 2p+1
            #pragma unroll
            for (int p = 0; p < 4; p++)
                ldsm_x4_t(b[p], smb + SM_B + ks * 16 * SSTR + b_off + p * 32);

            #pragma unroll
            for (int mf = 0; mf < 2; mf++)
                #pragma unroll
                for (int p = 0; p < 4; p++) {
                    mma_f16(acc[mf][2 * p],     a[mf], &b[p][0]);
                    mma_f16(acc[mf][2 * p + 1], a[mf], &b[p][2]);
                }
        }

        // ---- epilogue: pack column pairs as half2 ----
        #pragma unroll
        for (int mf = 0; mf < 2; mf++) {
            #pragma unroll
            for (int nf = 0; nf < 8; nf++) {
                size_t row = (size_t)(r0 + mrow + mf * 16 + g);
                size_t nn  = (size_t)(n0 + ncol + nf * 8 + t * 2);
                __half2 h0 = __floats2half2_rn(acc[mf][nf][0], acc[mf][nf][1]);
                __half2 h1 = __floats2half2_rn(acc[mf][nf][2], acc[mf][nf][3]);
                *(uint32_t*)(g_table + row * NPOS + nn)        = *(uint32_t*)&h0;
                *(uint32_t*)(g_table + (row + 8) * NPOS + nn)  = *(uint32_t*)&h1;
            }
        }
        __syncthreads();   // B smem reused next iteration
    }
}

// ============================================================================
// Kernel B: per row — sigmoid, reversed cumsum, clamp, interp gather.
// Streaming cache hints (.cs) on the single-use attn/table/out streams.
// ============================================================================
__global__ __launch_bounds__(256)
void cope_gather_kernel(const float* __restrict__ attn,   // [R,2048]
                        const int*   __restrict__ nposp,
                        float*       __restrict__ out) {  // [R,2048]
    __shared__ __half    tabh[NPOS];
    __shared__ uint32_t  tab2u[NPOS];
    __shared__ float     wsum[8];

    const int row  = blockIdx.x;
    const int tid  = threadIdx.x;
    const int lane = tid & 31;
    const int wid  = tid >> 5;

    ((uint32_t*)tabh)[tid] =
        __ldcs(((const uint32_t*)(g_table + (size_t)row * NPOS)) + tid);

    const float* arow = attn + (size_t)row * K_DIM + tid * 8;
    float4 v0 = __ldcs((const float4*)(arow));
    float4 v1 = __ldcs((const float4*)(arow + 4));
    float gg[8] = {v0.x, v0.y, v0.z, v0.w, v1.x, v1.y, v1.z, v1.w};
    #pragma unroll
    for (int j = 0; j < 8; j++)
        gg[j] = __fdividef(1.0f, 1.0f + __expf(-gg[j]));

    __syncthreads();
    {
        __half a = tabh[tid], b = tabh[tid + 1];
        __half2 h; h.x = a; h.y = b;
        tab2u[tid] = *(uint32_t*)&h;
        int i2 = tid + 256;
        __half a2 = tabh[i2];
        __half b2 = (i2 == NPOS - 1) ? a2 : tabh[i2 + 1];
        __half2 h2; h2.x = a2; h2.y = b2;
        tab2u[i2] = *(uint32_t*)&h2;
    }

    float ls[8];
    ls[7] = gg[7];
    #pragma unroll
    for (int j = 6; j >= 0; j--) ls[j] = gg[j] + ls[j + 1];

    float v = ls[0];
    #pragma unroll
    for (int d = 1; d < 32; d <<= 1) {
        float tt = __shfl_up_sync(0xffffffffu, v, d);
        if (lane >= d) v += tt;
    }
    if (lane == 31) wsum[wid] = v;
    __syncthreads();

    float wpre = 0.0f, total = 0.0f;
    #pragma unroll
    for (int w = 0; w < 8; w++) {
        float x = wsum[w];
        total += x;
        if (w < wid) wpre += x;
    }
    float offset = total - (wpre + v);

    const float npmf = (float)(*nposp - 1);

    float oo[8];
    #pragma unroll
    for (int j = 0; j < 8; j++) {
        float p  = fminf(offset + ls[j], npmf);
        float pf = floorf(p);
        float w  = p - pf;
        uint32_t pv = tab2u[(int)pf];
        float2 f = __half22float2(*(__half2*)&pv);
        oo[j] = fmaf(w, f.y - f.x, f.x);
    }

    float* orow = out + (size_t)row * K_DIM + tid * 8;
    __stcs((float4*)(orow),     make_float4(oo[0], oo[1], oo[2], oo[3]));
    __stcs((float4*)(orow + 4), make_float4(oo[4], oo[5], oo[6], oo[7]));
}

// ---------------------------------------------------------------------------
extern "C" void kernel_launch(void* const* d_in, const int* in_sizes, int n_in,
                              void* d_out, int out_size) {
    const float* q    = (const float*)d_in[0];   // [B,H,Q,D]
    const float* attn = (const float*)d_in[1];   // [B,H,Q,K]
    const float* pe   = (const float*)d_in[2];   // [1,D,NPOS]
    const int*   npos = (const int*)d_in[3];
    float*       out  = (float*)d_out;

    const int R = in_sizes[0] / D_DIM;           // 49152

    cudaFuncSetAttribute(cope_gemm_mma,
                         cudaFuncAttributeMaxDynamicSharedMemorySize, SM_TOTAL);
    cope_gemm_mma<<<R / 128, 256, SM_TOTAL>>>(q, pe);

    cope_gather_kernel<<<R, 256>>>(attn, npos, out);

    (void)n_in; (void)out_size;
}

// round 13
// speedup vs baseline: 1.4051x; 1.0450x over previous
#include <cuda_runtime.h>
#include <cuda_fp16.h>
#include <cstdint>

#define D_DIM   128
#define NPOS    512
#define K_DIM   2048
#define R_MAX   49152    // B*H*Q = 2*12*2048

// 50 MB scratch: fp16 interpolation tables (512 entries per (b,h,q) row).
__device__ __half g_table[(size_t)R_MAX * NPOS];
// 128 KB: P pre-converted to fp16 (row-major [128][512]).
__device__ __half g_p16[(size_t)D_DIM * NPOS];

// ---------------------------------------------------------------------------
// mma.sync m16n8k16 row.col f32.f16.f16.f32  (tensor pipe, sm_80+ PTX)
// ---------------------------------------------------------------------------
__device__ __forceinline__ void mma_f16(float* d, const uint32_t* a, const uint32_t* b) {
    asm volatile(
        "mma.sync.aligned.m16n8k16.row.col.f32.f16.f16.f32 "
        "{%0,%1,%2,%3}, {%4,%5,%6,%7}, {%8,%9}, {%0,%1,%2,%3};"
        : "+f"(d[0]), "+f"(d[1]), "+f"(d[2]), "+f"(d[3])
        : "r"(a[0]), "r"(a[1]), "r"(a[2]), "r"(a[3]), "r"(b[0]), "r"(b[1]));
}

__device__ __forceinline__ void ldsm_x4(uint32_t* r, uint32_t addr) {
    asm volatile("ldmatrix.sync.aligned.m8n8.x4.shared.b16 {%0,%1,%2,%3}, [%4];"
        : "=r"(r[0]), "=r"(r[1]), "=r"(r[2]), "=r"(r[3]) : "r"(addr));
}
__device__ __forceinline__ void ldsm_x4_t(uint32_t* r, uint32_t addr) {
    asm volatile("ldmatrix.sync.aligned.m8n8.x4.trans.shared.b16 {%0,%1,%2,%3}, [%4];"
        : "=r"(r[0]), "=r"(r[1]), "=r"(r[2]), "=r"(r[3]) : "r"(addr));
}

__device__ __forceinline__ uint32_t smem_u32(const void* p) {
    uint32_t a;
    asm("{ .reg .u64 t; cvta.to.shared.u64 t, %1; cvt.u32.u64 %0, t; }" : "=r"(a) : "l"(p));
    return a;
}

__device__ __forceinline__ void cp_async16(uint32_t dst, const void* src) {
    asm volatile("cp.async.ca.shared.global [%0], [%1], 16;"
        :: "r"(dst), "l"(src) : "memory");
}
__device__ __forceinline__ void cp_async_commit() {
    asm volatile("cp.async.commit_group;" ::: "memory");
}
__device__ __forceinline__ void cp_async_wait_all() {
    asm volatile("cp.async.wait_group 0;" ::: "memory");
}

// ============================================================================
// Kernel 0: convert P [128,512] fp32 -> fp16 (one-time, ~2 us).
// ============================================================================
__global__ __launch_bounds__(256)
void cvt_p_kernel(const float* __restrict__ P) {
    int i = (blockIdx.x * 256 + threadIdx.x) * 8;
    float4 a = *(const float4*)(P + i);
    float4 b = *(const float4*)(P + i + 4);
    __half2 h0 = __floats2half2_rn(a.x, a.y);
    __half2 h1 = __floats2half2_rn(a.z, a.w);
    __half2 h2 = __floats2half2_rn(b.x, b.y);
    __half2 h3 = __floats2half2_rn(b.z, b.w);
    uint4 w;
    w.x = *(uint32_t*)&h0; w.y = *(uint32_t*)&h1;
    w.z = *(uint32_t*)&h2; w.w = *(uint32_t*)&h3;
    *(uint4*)(g_p16 + i) = w;
}

// ============================================================================
// Kernel A: T[R,512] = Q[R,128] @ P[128,512], single-pass fp16 mma.
// One block per 128-row stripe (384 blocks, occ 2), A staged once (fp32 LDG
// + cvt), B double-buffered via cp.async from pre-converted g_p16: subtile
// ns+1's copy overlaps subtile ns's MMA+epilogue. 256 threads, 8 warps
// (4M x 2N), warp tile m32 x n64, smem 104.4 KB, ~100 regs.
// ============================================================================
#define SSTR      272
#define SM_A      0
#define SM_B0     34816          // 128*272
#define SM_B1     69632
#define SM_TOTAL  104448

__global__ __launch_bounds__(256, 2)
void cope_gemm_mma(const float* __restrict__ Q) {   // [R,128]
    extern __shared__ char sm[];
    const int tid  = threadIdx.x;
    const int lane = tid & 31;
    const int wid  = tid >> 5;
    const int r0   = blockIdx.x * 128;

    const uint32_t smb = smem_u32(sm);

    // ---- B cp.async indices: thread -> (k row, 128-byte half-row) ----
    const int bk  = tid >> 1;              // 0..127
    const int bcb = (tid & 1) * 128;       // byte offset within 256 B subtile row
    const char* psrc = (const char*)g_p16 + (size_t)bk * (NPOS * 2) + bcb;
    const uint32_t bdst = (uint32_t)(bk * SSTR + bcb);

    // ---- kick off B subtile 0 into buffer 0 ----
    #pragma unroll
    for (int i = 0; i < 8; i++)
        cp_async16(smb + SM_B0 + bdst + i * 16, psrc + i * 16);
    cp_async_commit();

    // ---- stage A tile ONCE: 128 rows x K=128, fp32 -> fp16, [m][k] ----
    {
        int r  = tid >> 1;                 // 0..127
        int c0 = (tid & 1) * 64;           // 64 k-floats per thread
        const float4* src = (const float4*)(Q + (size_t)(r0 + r) * D_DIM + c0);
        char* dst = sm + SM_A + r * SSTR + c0 * 2;
        #pragma unroll
        for (int i = 0; i < 16; i++) {
            float4 v = __ldcs(src + i);
            __half2 h0 = __floats2half2_rn(v.x, v.y);
            __half2 h1 = __floats2half2_rn(v.z, v.w);
            uint2 w;
            w.x = *(uint32_t*)&h0;
            w.y = *(uint32_t*)&h1;
            *(uint2*)(dst + i * 8) = w;
        }
    }

    const int g = lane >> 2;               // 0..7
    const int t = lane & 3;                // 0..3
    const int mrow = (wid & 3) * 32;       // 4 warps along M
    const int ncol = (wid >> 2) * 64;      // 2 warps along N

    const uint32_t a_off = (uint32_t)((mrow + ((lane >> 3) & 1) * 8 + (lane & 7)) * SSTR
                                      + (lane >> 4) * 16);
    const uint32_t b_off = (uint32_t)((((lane >> 3) & 1) * 8 + (lane & 7)) * SSTR
                                      + (lane >> 4) * 16 + ncol * 2);

    #pragma unroll
    for (int ns = 0; ns < 4; ns++) {
        cp_async_wait_all();
        __syncthreads();   // B(ns) + (ns==0: A STS) visible; prev MMA reads done

        // prefetch B(ns+1) into the other buffer (overlaps MMA + epilogue)
        if (ns < 3) {
            const uint32_t nxt = (ns & 1) ? SM_B0 : SM_B1;
            #pragma unroll
            for (int i = 0; i < 8; i++)
                cp_async16(smb + nxt + bdst + i * 16,
                           psrc + (ns + 1) * 256 + i * 16);
            cp_async_commit();
        }

        const uint32_t cur = (ns & 1) ? SM_B1 : SM_B0;
        const int n0 = ns * 128;

        float acc[2][8][4];                // [mf][nf][c]
        #pragma unroll
        for (int mf = 0; mf < 2; mf++)
            #pragma unroll
            for (int nf = 0; nf < 8; nf++)
                #pragma unroll
                for (int c = 0; c < 4; c++) acc[mf][nf][c] = 0.0f;

        #pragma unroll
        for (int ks = 0; ks < 8; ks++) {
            const uint32_t kb = ks * 32;   // A byte offset along k
            uint32_t a[2][4];
            #pragma unroll
            for (int mf = 0; mf < 2; mf++)
                ldsm_x4(a[mf], smb + SM_A + mf * 16 * SSTR + a_off + kb);
            uint32_t b[4][4];              // p covers nf=2p, 2p+1
            #pragma unroll
            for (int p = 0; p < 4; p++)
                ldsm_x4_t(b[p], smb + cur + ks * 16 * SSTR + b_off + p * 32);

            #pragma unroll
            for (int mf = 0; mf < 2; mf++)
                #pragma unroll
                for (int p = 0; p < 4; p++) {
                    mma_f16(acc[mf][2 * p],     a[mf], &b[p][0]);
                    mma_f16(acc[mf][2 * p + 1], a[mf], &b[p][2]);
                }
        }

        // ---- epilogue: pack column pairs as half2 ----
        #pragma unroll
        for (int mf = 0; mf < 2; mf++) {
            #pragma unroll
            for (int nf = 0; nf < 8; nf++) {
                size_t row = (size_t)(r0 + mrow + mf * 16 + g);
                size_t nn  = (size_t)(n0 + ncol + nf * 8 + t * 2);
                __half2 h0 = __floats2half2_rn(acc[mf][nf][0], acc[mf][nf][1]);
                __half2 h1 = __floats2half2_rn(acc[mf][nf][2], acc[mf][nf][3]);
                *(uint32_t*)(g_table + row * NPOS + nn)        = *(uint32_t*)&h0;
                *(uint32_t*)(g_table + (row + 8) * NPOS + nn)  = *(uint32_t*)&h1;
            }
        }
    }
}

// ============================================================================
// Kernel B: per row — sigmoid, reversed cumsum, clamp, interp gather.
// Streaming cache hints (.cs) on the single-use attn/table/out streams.
// ============================================================================
__global__ __launch_bounds__(256)
void cope_gather_kernel(const float* __restrict__ attn,   // [R,2048]
                        const int*   __restrict__ nposp,
                        float*       __restrict__ out) {  // [R,2048]
    __shared__ __half    tabh[NPOS];
    __shared__ uint32_t  tab2u[NPOS];
    __shared__ float     wsum[8];

    const int row  = blockIdx.x;
    const int tid  = threadIdx.x;
    const int lane = tid & 31;
    const int wid  = tid >> 5;

    ((uint32_t*)tabh)[tid] =
        __ldcs(((const uint32_t*)(g_table + (size_t)row * NPOS)) + tid);

    const float* arow = attn + (size_t)row * K_DIM + tid * 8;
    float4 v0 = __ldcs((const float4*)(arow));
    float4 v1 = __ldcs((const float4*)(arow + 4));
    float gg[8] = {v0.x, v0.y, v0.z, v0.w, v1.x, v1.y, v1.z, v1.w};
    #pragma unroll
    for (int j = 0; j < 8; j++)
        gg[j] = __fdividef(1.0f, 1.0f + __expf(-gg[j]));

    __syncthreads();
    {
        __half a = tabh[tid], b = tabh[tid + 1];
        __half2 h; h.x = a; h.y = b;
        tab2u[tid] = *(uint32_t*)&h;
        int i2 = tid + 256;
        __half a2 = tabh[i2];
        __half b2 = (i2 == NPOS - 1) ? a2 : tabh[i2 + 1];
        __half2 h2; h2.x = a2; h2.y = b2;
        tab2u[i2] = *(uint32_t*)&h2;
    }

    float ls[8];
    ls[7] = gg[7];
    #pragma unroll
    for (int j = 6; j >= 0; j--) ls[j] = gg[j] + ls[j + 1];

    float v = ls[0];
    #pragma unroll
    for (int d = 1; d < 32; d <<= 1) {
        float tt = __shfl_up_sync(0xffffffffu, v, d);
        if (lane >= d) v += tt;
    }
    if (lane == 31) wsum[wid] = v;
    __syncthreads();

    float wpre = 0.0f, total = 0.0f;
    #pragma unroll
    for (int w = 0; w < 8; w++) {
        float x = wsum[w];
        total += x;
        if (w < wid) wpre += x;
    }
    float offset = total - (wpre + v);

    const float npmf = (float)(*nposp - 1);

    float oo[8];
    #pragma unroll
    for (int j = 0; j < 8; j++) {
        float p  = fminf(offset + ls[j], npmf);
        float pf = floorf(p);
        float w  = p - pf;
        uint32_t pv = tab2u[(int)pf];
        float2 f = __half22float2(*(__half2*)&pv);
        oo[j] = fmaf(w, f.y - f.x, f.x);
    }

    float* orow = out + (size_t)row * K_DIM + tid * 8;
    __stcs((float4*)(orow),     make_float4(oo[0], oo[1], oo[2], oo[3]));
    __stcs((float4*)(orow + 4), make_float4(oo[4], oo[5], oo[6], oo[7]));
}

// ---------------------------------------------------------------------------
extern "C" void kernel_launch(void* const* d_in, const int* in_sizes, int n_in,
                              void* d_out, int out_size) {
    const float* q    = (const float*)d_in[0];   // [B,H,Q,D]
    const float* attn = (const float*)d_in[1];   // [B,H,Q,K]
    const float* pe   = (const float*)d_in[2];   // [1,D,NPOS]
    const int*   npos = (const int*)d_in[3];
    float*       out  = (float*)d_out;

    const int R = in_sizes[0] / D_DIM;           // 49152

    cvt_p_kernel<<<(D_DIM * NPOS) / (256 * 8), 256>>>(pe);

    cudaFuncSetAttribute(cope_gemm_mma,
                         cudaFuncAttributeMaxDynamicSharedMemorySize, SM_TOTAL);
    cope_gemm_mma<<<R / 128, 256, SM_TOTAL>>>(q);

    cope_gather_kernel<<<R, 256>>>(attn, npos, out);

    (void)n_in; (void)out_size;
}